// round 16
// baseline (speedup 1.0000x reference)
#include <cuda_runtime.h>
#include <cuda_fp16.h>
#include <math.h>
#include <stdint.h>

// Problem constants (fixed by setup_inputs)
#define EMAX 500000
#define NEMAX 100000
#define NRMAX 1008
#define DD 128
#define KTOT 384

// ---------- device scratch (static; no allocation allowed) ----------
__device__ __align__(16) float g_wa[KTOT];          // W @ a
__device__ float g_p[NEMAX];                        // emb[n] . wa[0:128]
__device__ float g_q[NEMAX];                        // emb[n] . wa[256:384]
__device__ float g_s[NRMAX];                        // rel[r] . wa[128:256]
__device__ __align__(8) float g_score[EMAX];        // exp(score) per edge
__device__ float g_denom[NEMAX];                    // segment sum of exp
__device__ __align__(16) float g_acc[NEMAX * DD];   // emb@W1, then += scatter
__device__ __align__(16) __half g_embW3h[NEMAX * DD]; // emb@W3 (fp16)
__device__ __align__(16) __half g_relW2h[NRMAX * DD]; // rel@W2 (fp16)

// ---------- helpers ----------
__device__ __forceinline__ uint32_t f2tf(float f) {
    uint32_t r;
    asm("cvt.rna.tf32.f32 %0, %1;" : "=r"(r) : "f"(f));
    return r;
}

// ---------- fused prep (block ranges): wa = W@a | denom=0 | relW2h rows ----------
__global__ __launch_bounds__(256) void k_prep(const float* __restrict__ W,
                                              const float* __restrict__ a,
                                              const float* __restrict__ rel,
                                              int NE, int NR, int nbden) {
    int b = blockIdx.x;
    int tid = threadIdx.x;
    if (b < 2) {
        int i = b * 256 + tid;
        if (i < KTOT) {
            const float* row = W + (size_t)i * DD;
            float s0 = 0.f, s1 = 0.f, s2 = 0.f, s3 = 0.f;
            #pragma unroll
            for (int u = 0; u < DD; u += 4) {
                s0 = fmaf(row[u],     a[u],     s0);
                s1 = fmaf(row[u + 1], a[u + 1], s1);
                s2 = fmaf(row[u + 2], a[u + 2], s2);
                s3 = fmaf(row[u + 3], a[u + 3], s3);
            }
            g_wa[i] = (s0 + s1) + (s2 + s3);
        }
        return;
    }
    if (b < 2 + nbden) {
        int i = (b - 2) * 256 + tid;
        if (i < NE) g_denom[i] = 0.f;
        return;
    }
    __shared__ float srel[2][DD];
    int rb = b - 2 - nbden;
    int half = tid >> 7;
    int u = tid & 127;
    int rn = rb * 2 + half;
    float rv = 0.f;
    if (rn < NR) rv = rel[(size_t)rn * DD + u];
    srel[half][u] = rv;
    __syncthreads();
    if (rn >= NR) return;
    const float* wcol = W + (size_t)128 * DD + u;
    float s0 = 0.f, s1 = 0.f, s2 = 0.f, s3 = 0.f;
    #pragma unroll
    for (int k = 0; k < DD; k += 4) {
        s0 = fmaf(srel[half][k],     wcol[(size_t)k * DD],       s0);
        s1 = fmaf(srel[half][k + 1], wcol[(size_t)(k + 1) * DD], s1);
        s2 = fmaf(srel[half][k + 2], wcol[(size_t)(k + 2) * DD], s2);
        s3 = fmaf(srel[half][k + 3], wcol[(size_t)(k + 3) * DD], s3);
    }
    g_relW2h[rn * DD + u] = __float2half_rn((s0 + s1) + (s2 + s3));
}

// ---------- tf32 tensor-core GEMM: [acc(f32) | embW3(f16)] = emb @ [W1 | W3] ----------
// 64x256 block tile, 256 threads, K-chunk 32; fused p/q entity dots in fp32.
// Tail blocks (>= nbm) compute s[r] = rel[r] . wa[128:256], one warp per relation.
__global__ __launch_bounds__(256) void k_mm(const float* __restrict__ emb,
                                            const float* __restrict__ W,
                                            const float* __restrict__ rel,
                                            int NE, int NR, int nbm) {
    if (blockIdx.x >= nbm) {
        int wid = threadIdx.x >> 5;
        int lane = threadIdx.x & 31;
        int rn = (blockIdx.x - nbm) * 8 + wid;
        if (rn >= NR) return;
        float4 v  = ((const float4*)(rel + (size_t)rn * DD))[lane];
        float4 wa = ((const float4*)(g_wa + 128))[lane];
        float s = v.x*wa.x + v.y*wa.y + v.z*wa.z + v.w*wa.w;
        #pragma unroll
        for (int o = 16; o; o >>= 1) s += __shfl_xor_sync(0xffffffffu, s, o);
        if (lane == 0) g_s[rn] = s;
        return;
    }
    __shared__ uint32_t As[64 * 36];
    __shared__ uint32_t Bs[32 * 264];
    int tid  = threadIdx.x;
    int lane = tid & 31;
    int wid  = tid >> 5;
    int g  = lane >> 2;
    int t4 = lane & 3;
    int wm = wid >> 2;
    int wn = wid & 3;
    int n0 = blockIdx.x * 64;
    int arow = tid >> 3;
    int aq   = tid & 7;

    float c[2][8][4];
    #pragma unroll
    for (int i = 0; i < 2; i++)
        #pragma unroll
        for (int j = 0; j < 8; j++)
            #pragma unroll
            for (int k = 0; k < 4; k++) c[i][j][k] = 0.f;

    float pp0 = 0.f, qq0 = 0.f, pp1 = 0.f, qq1 = 0.f;

    #pragma unroll 1
    for (int kc = 0; kc < 4; kc++) {
        int k0 = kc * 32;
        float4 wa0 = *(const float4*)&g_wa[k0 + aq * 4];
        float4 wa2 = *(const float4*)&g_wa[256 + k0 + aq * 4];
        #pragma unroll
        for (int i = 0; i < 2; i++) {
            int row = arow + i * 32;
            int n = n0 + row;
            float4 v = make_float4(0.f, 0.f, 0.f, 0.f);
            if (n < NE) v = *(const float4*)(emb + (size_t)n * DD + k0 + aq * 4);
            *(uint4*)&As[row * 36 + aq * 4] =
                make_uint4(f2tf(v.x), f2tf(v.y), f2tf(v.z), f2tf(v.w));
            float pd = v.x*wa0.x + v.y*wa0.y + v.z*wa0.z + v.w*wa0.w;
            float qd = v.x*wa2.x + v.y*wa2.y + v.z*wa2.z + v.w*wa2.w;
            if (i == 0) { pp0 += pd; qq0 += qd; }
            else        { pp1 += pd; qq1 += qd; }
        }
        #pragma unroll
        for (int i = 0; i < 8; i++) {
            int idx = tid + i * 256;
            int k  = idx >> 6;
            int u  = (idx & 63) * 4;
            const float* src = (u < 128)
                ? (W + (size_t)(k0 + k) * DD + u)
                : (W + (size_t)(256 + k0 + k) * DD + (u - 128));
            float4 v = *(const float4*)src;
            *(uint4*)&Bs[k * 264 + u] =
                make_uint4(f2tf(v.x), f2tf(v.y), f2tf(v.z), f2tf(v.w));
        }
        __syncthreads();
        #pragma unroll
        for (int ks = 0; ks < 4; ks++) {
            int kk = ks * 8;
            uint32_t a[2][4], b[8][2];
            #pragma unroll
            for (int fm = 0; fm < 2; fm++) {
                int mr = wm * 32 + fm * 16 + g;
                a[fm][0] = As[mr * 36 + kk + t4];
                a[fm][1] = As[(mr + 8) * 36 + kk + t4];
                a[fm][2] = As[mr * 36 + kk + t4 + 4];
                a[fm][3] = As[(mr + 8) * 36 + kk + t4 + 4];
            }
            #pragma unroll
            for (int fn = 0; fn < 8; fn++) {
                int col = wn * 64 + fn * 8 + g;
                b[fn][0] = Bs[(kk + t4) * 264 + col];
                b[fn][1] = Bs[(kk + t4 + 4) * 264 + col];
            }
            #pragma unroll
            for (int fm = 0; fm < 2; fm++)
                #pragma unroll
                for (int fn = 0; fn < 8; fn++)
                    asm volatile(
                        "mma.sync.aligned.m16n8k8.row.col.f32.tf32.tf32.f32 "
                        "{%0,%1,%2,%3}, {%4,%5,%6,%7}, {%8,%9}, {%0,%1,%2,%3};"
                        : "+f"(c[fm][fn][0]), "+f"(c[fm][fn][1]),
                          "+f"(c[fm][fn][2]), "+f"(c[fm][fn][3])
                        : "r"(a[fm][0]), "r"(a[fm][1]), "r"(a[fm][2]), "r"(a[fm][3]),
                          "r"(b[fn][0]), "r"(b[fn][1]));
        }
        __syncthreads();
    }

    #pragma unroll
    for (int o = 4; o; o >>= 1) {
        pp0 += __shfl_xor_sync(0xffffffffu, pp0, o);
        qq0 += __shfl_xor_sync(0xffffffffu, qq0, o);
        pp1 += __shfl_xor_sync(0xffffffffu, pp1, o);
        qq1 += __shfl_xor_sync(0xffffffffu, qq1, o);
    }
    if ((tid & 7) == 0) {
        int na = n0 + arow;
        if (na < NE)      { g_p[na] = pp0;      g_q[na] = qq0; }
        int nb = na + 32;
        if (nb < NE)      { g_p[nb] = pp1;      g_q[nb] = qq1; }
    }

    if (wn < 2) {
        int colbase = wn * 64;
        #pragma unroll
        for (int fm = 0; fm < 2; fm++) {
            #pragma unroll
            for (int fn = 0; fn < 8; fn++) {
                int col = colbase + fn * 8 + t4 * 2;
                int r0 = n0 + wm * 32 + fm * 16 + g;
                if (r0 < NE)
                    *(float2*)&g_acc[(size_t)r0 * DD + col] =
                        make_float2(c[fm][fn][0], c[fm][fn][1]);
                int r1 = r0 + 8;
                if (r1 < NE)
                    *(float2*)&g_acc[(size_t)r1 * DD + col] =
                        make_float2(c[fm][fn][2], c[fm][fn][3]);
            }
        }
    } else {
        int colbase = (wn - 2) * 64;
        #pragma unroll
        for (int fm = 0; fm < 2; fm++) {
            #pragma unroll
            for (int fn = 0; fn < 8; fn++) {
                int col = colbase + fn * 8 + t4 * 2;
                int r0 = n0 + wm * 32 + fm * 16 + g;
                if (r0 < NE)
                    *(__half2*)&g_embW3h[(size_t)r0 * DD + col] =
                        __floats2half2_rn(c[fm][fn][0], c[fm][fn][1]);
                int r1 = r0 + 8;
                if (r1 < NE)
                    *(__half2*)&g_embW3h[(size_t)r1 * DD + col] =
                        __floats2half2_rn(c[fm][fn][2], c[fm][fn][3]);
            }
        }
    }
}

// single fused score pass: score -> exp -> denom accumulation
__global__ void k_score(const int* __restrict__ h, const int* __restrict__ r,
                        const int* __restrict__ t, const float* __restrict__ ab, int E) {
    int e = blockIdx.x * blockDim.x + threadIdx.x;
    if (e >= E) return;
    int hn = h[e];
    float x = g_p[hn] + g_s[r[e]] + g_q[t[e]] + ab[0];
    float sc = x >= 0.f ? x : 0.04f * x;
    float ex = expf(sc);
    g_score[e] = ex;
    atomicAdd(&g_denom[hn], ex);
}

// 16 lanes per edge (2 edges per warp): acc[h] += alpha * (relW2[r] + embW3[t])
// halves warp-level memory instruction count vs 32-lane/edge
__global__ __launch_bounds__(256) void k_scatter(const int* __restrict__ h,
                                                 const int* __restrict__ r,
                                                 const int* __restrict__ t, int E) {
    int idx = blockIdx.x * blockDim.x + threadIdx.x;
    int e = idx >> 4;
    int l = idx & 15;
    if (e >= E) return;
    int hn = h[e], rn = r[e], tn = t[e];
    float sc = g_score[e];
    float dn = g_denom[hn];
    // 8 halves per lane from each table via one 16B load (256B/row, 2 wavefronts)
    uint4 ru = ((const uint4*)(g_relW2h + (size_t)rn * DD))[l];
    uint4 tu = ((const uint4*)(g_embW3h + (size_t)tn * DD))[l];
    float alpha = sc / dn;
    float2 fr0 = __half22float2(*(__half2*)&ru.x), fr1 = __half22float2(*(__half2*)&ru.y);
    float2 fr2 = __half22float2(*(__half2*)&ru.z), fr3 = __half22float2(*(__half2*)&ru.w);
    float2 ft0 = __half22float2(*(__half2*)&tu.x), ft1 = __half22float2(*(__half2*)&tu.y);
    float2 ft2 = __half22float2(*(__half2*)&tu.z), ft3 = __half22float2(*(__half2*)&tu.w);
    float4* dst = ((float4*)g_acc) + (size_t)hn * 32 + l * 2;
    atomicAdd(dst,     make_float4(alpha * (fr0.x + ft0.x), alpha * (fr0.y + ft0.y),
                                   alpha * (fr1.x + ft1.x), alpha * (fr1.y + ft1.y)));
    atomicAdd(dst + 1, make_float4(alpha * (fr2.x + ft2.x), alpha * (fr2.y + ft2.y),
                                   alpha * (fr3.x + ft3.x), alpha * (fr3.y + ft3.y)));
}

// out[n] = relu(mask(n) * acc[n] + bias)
__global__ void k_out(const float* __restrict__ bias, float* __restrict__ out, int NE) {
    int idx = blockIdx.x * blockDim.x + threadIdx.x;
    if (idx >= NE * 32) return;
    int n = idx >> 5, u4 = idx & 31;
    float m = g_denom[n] > 0.f ? 1.f : 0.f;
    float4 a = ((const float4*)g_acc)[idx];
    float4 b = ((const float4*)bias)[u4];
    float4 o;
    o.x = fmaxf(fmaf(a.x, m, b.x), 0.f);
    o.y = fmaxf(fmaf(a.y, m, b.y), 0.f);
    o.z = fmaxf(fmaf(a.z, m, b.z), 0.f);
    o.w = fmaxf(fmaf(a.w, m, b.w), 0.f);
    ((float4*)out)[idx] = o;
}

extern "C" void kernel_launch(void* const* d_in, const int* in_sizes, int n_in,
                              void* d_out, int out_size) {
    const int*   h    = (const int*)d_in[0];
    const int*   r    = (const int*)d_in[1];
    const int*   t    = (const int*)d_in[2];
    const float* emb  = (const float*)d_in[3];
    const float* rel  = (const float*)d_in[4];
    const float* W    = (const float*)d_in[5];
    const float* a    = (const float*)d_in[6];
    const float* ab   = (const float*)d_in[7];
    const float* bias = (const float*)d_in[8];
    float* out = (float*)d_out;

    int E  = in_sizes[0];
    int NE = in_sizes[3] / DD;
    int NR = in_sizes[4] / DD;

    int nbden = (NE + 255) / 256;
    int nbrel = (NR + 1) / 2;
    int nbm   = (NE + 63) / 64;
    int nbs   = (NR + 7) / 8;

    k_prep<<<2 + nbden + nbrel, 256>>>(W, a, rel, NE, NR, nbden);
    k_mm<<<nbm + nbs, 256>>>(emb, W, rel, NE, NR, nbm);
    k_score<<<(E + 255) / 256, 256>>>(h, r, t, ab, E);
    k_scatter<<<(E * 16 + 255) / 256, 256>>>(h, r, t, E);
    k_out<<<(NE * 32 + 255) / 256, 256>>>(bias, out, NE);
}

// round 17
// speedup vs baseline: 1.0791x; 1.0791x over previous
#include <cuda_runtime.h>
#include <cuda_fp16.h>
#include <math.h>
#include <stdint.h>

// Problem constants (fixed by setup_inputs)
#define EMAX 500000
#define NEMAX 100000
#define NRMAX 1008
#define DD 128
#define KTOT 384

// ---------- device scratch (static; no allocation allowed) ----------
__device__ __align__(16) float g_wa[KTOT];          // W @ a
__device__ float g_p[NEMAX];                        // emb[n] . wa[0:128]
__device__ float g_q[NEMAX];                        // emb[n] . wa[256:384]
__device__ float g_s[NRMAX];                        // rel[r] . wa[128:256]
__device__ __align__(8) float g_score[EMAX];        // exp(score) per edge
__device__ float g_denom[NEMAX];                    // segment sum of exp
__device__ __align__(16) float g_acc[NEMAX * DD];   // emb@W1, then += scatter
__device__ __align__(16) __half g_embW3h[NEMAX * DD]; // emb@W3 (fp16)
__device__ __align__(16) __half g_relW2h[NRMAX * DD]; // rel@W2 (fp16)

// ---------- helpers ----------
__device__ __forceinline__ uint32_t f2tf(float f) {
    uint32_t r;
    asm("cvt.rna.tf32.f32 %0, %1;" : "=r"(r) : "f"(f));
    return r;
}

// ---------- fused prep (block ranges): wa = W@a | denom=0 | relW2h rows ----------
__global__ __launch_bounds__(256) void k_prep(const float* __restrict__ W,
                                              const float* __restrict__ a,
                                              const float* __restrict__ rel,
                                              int NE, int NR, int nbden) {
    int b = blockIdx.x;
    int tid = threadIdx.x;
    if (b < 2) {
        int i = b * 256 + tid;
        if (i < KTOT) {
            const float* row = W + (size_t)i * DD;
            float s0 = 0.f, s1 = 0.f, s2 = 0.f, s3 = 0.f;
            #pragma unroll
            for (int u = 0; u < DD; u += 4) {
                s0 = fmaf(row[u],     a[u],     s0);
                s1 = fmaf(row[u + 1], a[u + 1], s1);
                s2 = fmaf(row[u + 2], a[u + 2], s2);
                s3 = fmaf(row[u + 3], a[u + 3], s3);
            }
            g_wa[i] = (s0 + s1) + (s2 + s3);
        }
        return;
    }
    if (b < 2 + nbden) {
        int i = (b - 2) * 256 + tid;
        if (i < NE) g_denom[i] = 0.f;
        return;
    }
    __shared__ float srel[2][DD];
    int rb = b - 2 - nbden;
    int half = tid >> 7;
    int u = tid & 127;
    int rn = rb * 2 + half;
    float rv = 0.f;
    if (rn < NR) rv = rel[(size_t)rn * DD + u];
    srel[half][u] = rv;
    __syncthreads();
    if (rn >= NR) return;
    const float* wcol = W + (size_t)128 * DD + u;
    float s0 = 0.f, s1 = 0.f, s2 = 0.f, s3 = 0.f;
    #pragma unroll
    for (int k = 0; k < DD; k += 4) {
        s0 = fmaf(srel[half][k],     wcol[(size_t)k * DD],       s0);
        s1 = fmaf(srel[half][k + 1], wcol[(size_t)(k + 1) * DD], s1);
        s2 = fmaf(srel[half][k + 2], wcol[(size_t)(k + 2) * DD], s2);
        s3 = fmaf(srel[half][k + 3], wcol[(size_t)(k + 3) * DD], s3);
    }
    g_relW2h[rn * DD + u] = __float2half_rn((s0 + s1) + (s2 + s3));
}

// ---------- tf32 tensor-core GEMM: [acc(f32) | embW3(f16)] = emb @ [W1 | W3] ----------
// 64x256 block tile, 256 threads, K-chunk 32; fused p/q entity dots in fp32.
// Tail blocks (>= nbm) compute s[r] = rel[r] . wa[128:256], one warp per relation.
__global__ __launch_bounds__(256) void k_mm(const float* __restrict__ emb,
                                            const float* __restrict__ W,
                                            const float* __restrict__ rel,
                                            int NE, int NR, int nbm) {
    if (blockIdx.x >= nbm) {
        int wid = threadIdx.x >> 5;
        int lane = threadIdx.x & 31;
        int rn = (blockIdx.x - nbm) * 8 + wid;
        if (rn >= NR) return;
        float4 v  = ((const float4*)(rel + (size_t)rn * DD))[lane];
        float4 wa = ((const float4*)(g_wa + 128))[lane];
        float s = v.x*wa.x + v.y*wa.y + v.z*wa.z + v.w*wa.w;
        #pragma unroll
        for (int o = 16; o; o >>= 1) s += __shfl_xor_sync(0xffffffffu, s, o);
        if (lane == 0) g_s[rn] = s;
        return;
    }
    __shared__ uint32_t As[64 * 36];
    __shared__ uint32_t Bs[32 * 264];
    int tid  = threadIdx.x;
    int lane = tid & 31;
    int wid  = tid >> 5;
    int g  = lane >> 2;
    int t4 = lane & 3;
    int wm = wid >> 2;
    int wn = wid & 3;
    int n0 = blockIdx.x * 64;
    int arow = tid >> 3;
    int aq   = tid & 7;

    float c[2][8][4];
    #pragma unroll
    for (int i = 0; i < 2; i++)
        #pragma unroll
        for (int j = 0; j < 8; j++)
            #pragma unroll
            for (int k = 0; k < 4; k++) c[i][j][k] = 0.f;

    float pp0 = 0.f, qq0 = 0.f, pp1 = 0.f, qq1 = 0.f;

    #pragma unroll 1
    for (int kc = 0; kc < 4; kc++) {
        int k0 = kc * 32;
        float4 wa0 = *(const float4*)&g_wa[k0 + aq * 4];
        float4 wa2 = *(const float4*)&g_wa[256 + k0 + aq * 4];
        #pragma unroll
        for (int i = 0; i < 2; i++) {
            int row = arow + i * 32;
            int n = n0 + row;
            float4 v = make_float4(0.f, 0.f, 0.f, 0.f);
            if (n < NE) v = *(const float4*)(emb + (size_t)n * DD + k0 + aq * 4);
            *(uint4*)&As[row * 36 + aq * 4] =
                make_uint4(f2tf(v.x), f2tf(v.y), f2tf(v.z), f2tf(v.w));
            float pd = v.x*wa0.x + v.y*wa0.y + v.z*wa0.z + v.w*wa0.w;
            float qd = v.x*wa2.x + v.y*wa2.y + v.z*wa2.z + v.w*wa2.w;
            if (i == 0) { pp0 += pd; qq0 += qd; }
            else        { pp1 += pd; qq1 += qd; }
        }
        #pragma unroll
        for (int i = 0; i < 8; i++) {
            int idx = tid + i * 256;
            int k  = idx >> 6;
            int u  = (idx & 63) * 4;
            const float* src = (u < 128)
                ? (W + (size_t)(k0 + k) * DD + u)
                : (W + (size_t)(256 + k0 + k) * DD + (u - 128));
            float4 v = *(const float4*)src;
            *(uint4*)&Bs[k * 264 + u] =
                make_uint4(f2tf(v.x), f2tf(v.y), f2tf(v.z), f2tf(v.w));
        }
        __syncthreads();
        #pragma unroll
        for (int ks = 0; ks < 4; ks++) {
            int kk = ks * 8;
            uint32_t a[2][4], b[8][2];
            #pragma unroll
            for (int fm = 0; fm < 2; fm++) {
                int mr = wm * 32 + fm * 16 + g;
                a[fm][0] = As[mr * 36 + kk + t4];
                a[fm][1] = As[(mr + 8) * 36 + kk + t4];
                a[fm][2] = As[mr * 36 + kk + t4 + 4];
                a[fm][3] = As[(mr + 8) * 36 + kk + t4 + 4];
            }
            #pragma unroll
            for (int fn = 0; fn < 8; fn++) {
                int col = wn * 64 + fn * 8 + g;
                b[fn][0] = Bs[(kk + t4) * 264 + col];
                b[fn][1] = Bs[(kk + t4 + 4) * 264 + col];
            }
            #pragma unroll
            for (int fm = 0; fm < 2; fm++)
                #pragma unroll
                for (int fn = 0; fn < 8; fn++)
                    asm volatile(
                        "mma.sync.aligned.m16n8k8.row.col.f32.tf32.tf32.f32 "
                        "{%0,%1,%2,%3}, {%4,%5,%6,%7}, {%8,%9}, {%0,%1,%2,%3};"
                        : "+f"(c[fm][fn][0]), "+f"(c[fm][fn][1]),
                          "+f"(c[fm][fn][2]), "+f"(c[fm][fn][3])
                        : "r"(a[fm][0]), "r"(a[fm][1]), "r"(a[fm][2]), "r"(a[fm][3]),
                          "r"(b[fn][0]), "r"(b[fn][1]));
        }
        __syncthreads();
    }

    #pragma unroll
    for (int o = 4; o; o >>= 1) {
        pp0 += __shfl_xor_sync(0xffffffffu, pp0, o);
        qq0 += __shfl_xor_sync(0xffffffffu, qq0, o);
        pp1 += __shfl_xor_sync(0xffffffffu, pp1, o);
        qq1 += __shfl_xor_sync(0xffffffffu, qq1, o);
    }
    if ((tid & 7) == 0) {
        int na = n0 + arow;
        if (na < NE)      { g_p[na] = pp0;      g_q[na] = qq0; }
        int nb = na + 32;
        if (nb < NE)      { g_p[nb] = pp1;      g_q[nb] = qq1; }
    }

    if (wn < 2) {
        int colbase = wn * 64;
        #pragma unroll
        for (int fm = 0; fm < 2; fm++) {
            #pragma unroll
            for (int fn = 0; fn < 8; fn++) {
                int col = colbase + fn * 8 + t4 * 2;
                int r0 = n0 + wm * 32 + fm * 16 + g;
                if (r0 < NE)
                    *(float2*)&g_acc[(size_t)r0 * DD + col] =
                        make_float2(c[fm][fn][0], c[fm][fn][1]);
                int r1 = r0 + 8;
                if (r1 < NE)
                    *(float2*)&g_acc[(size_t)r1 * DD + col] =
                        make_float2(c[fm][fn][2], c[fm][fn][3]);
            }
        }
    } else {
        int colbase = (wn - 2) * 64;
        #pragma unroll
        for (int fm = 0; fm < 2; fm++) {
            #pragma unroll
            for (int fn = 0; fn < 8; fn++) {
                int col = colbase + fn * 8 + t4 * 2;
                int r0 = n0 + wm * 32 + fm * 16 + g;
                if (r0 < NE)
                    *(__half2*)&g_embW3h[(size_t)r0 * DD + col] =
                        __floats2half2_rn(c[fm][fn][0], c[fm][fn][1]);
                int r1 = r0 + 8;
                if (r1 < NE)
                    *(__half2*)&g_embW3h[(size_t)r1 * DD + col] =
                        __floats2half2_rn(c[fm][fn][2], c[fm][fn][3]);
            }
        }
    }
}

// single fused score pass: score -> exp -> denom accumulation
__global__ void k_score(const int* __restrict__ h, const int* __restrict__ r,
                        const int* __restrict__ t, const float* __restrict__ ab, int E) {
    int e = blockIdx.x * blockDim.x + threadIdx.x;
    if (e >= E) return;
    int hn = h[e];
    float x = g_p[hn] + g_s[r[e]] + g_q[t[e]] + ab[0];
    float sc = x >= 0.f ? x : 0.04f * x;
    float ex = expf(sc);
    g_score[e] = ex;
    atomicAdd(&g_denom[hn], ex);
}

// one warp per edge: acc[h] += alpha * (relW2[r] + embW3[t]); fp16 gathers, fp32 RED.
// embW3h (25.6MB, no reuse) streamed with __ldcs so relW2h (258KB, hot) stays L1-resident.
__global__ __launch_bounds__(256) void k_scatter(const int* __restrict__ h,
                                                 const int* __restrict__ r,
                                                 const int* __restrict__ t, int E) {
    int e = (blockIdx.x * blockDim.x + threadIdx.x) >> 5;
    int lane = threadIdx.x & 31;
    if (e >= E) return;
    int hn = h[e], rn = r[e], tn = t[e];
    float sc = g_score[e];
    float dn = g_denom[hn];
    uint2 ru = ((const uint2*)(g_relW2h + (size_t)rn * DD))[lane];
    uint2 tu = __ldcs(((const uint2*)(g_embW3h + (size_t)tn * DD)) + lane);
    float alpha = sc / dn;
    float2 fr0 = __half22float2(*(__half2*)&ru.x), fr1 = __half22float2(*(__half2*)&ru.y);
    float2 ft0 = __half22float2(*(__half2*)&tu.x), ft1 = __half22float2(*(__half2*)&tu.y);
    float4* dst = ((float4*)g_acc) + (size_t)hn * 32 + lane;
    atomicAdd(dst, make_float4(alpha * (fr0.x + ft0.x), alpha * (fr0.y + ft0.y),
                               alpha * (fr1.x + ft1.x), alpha * (fr1.y + ft1.y)));
}

// out[n] = relu(mask(n) * acc[n] + bias)
__global__ void k_out(const float* __restrict__ bias, float* __restrict__ out, int NE) {
    int idx = blockIdx.x * blockDim.x + threadIdx.x;
    if (idx >= NE * 32) return;
    int n = idx >> 5, u4 = idx & 31;
    float m = g_denom[n] > 0.f ? 1.f : 0.f;
    float4 a = ((const float4*)g_acc)[idx];
    float4 b = ((const float4*)bias)[u4];
    float4 o;
    o.x = fmaxf(fmaf(a.x, m, b.x), 0.f);
    o.y = fmaxf(fmaf(a.y, m, b.y), 0.f);
    o.z = fmaxf(fmaf(a.z, m, b.z), 0.f);
    o.w = fmaxf(fmaf(a.w, m, b.w), 0.f);
    ((float4*)out)[idx] = o;
}

extern "C" void kernel_launch(void* const* d_in, const int* in_sizes, int n_in,
                              void* d_out, int out_size) {
    const int*   h    = (const int*)d_in[0];
    const int*   r    = (const int*)d_in[1];
    const int*   t    = (const int*)d_in[2];
    const float* emb  = (const float*)d_in[3];
    const float* rel  = (const float*)d_in[4];
    const float* W    = (const float*)d_in[5];
    const float* a    = (const float*)d_in[6];
    const float* ab   = (const float*)d_in[7];
    const float* bias = (const float*)d_in[8];
    float* out = (float*)d_out;

    int E  = in_sizes[0];
    int NE = in_sizes[3] / DD;
    int NR = in_sizes[4] / DD;

    int nbden = (NE + 255) / 256;
    int nbrel = (NR + 1) / 2;
    int nbm   = (NE + 63) / 64;
    int nbs   = (NR + 7) / 8;

    k_prep<<<2 + nbden + nbrel, 256>>>(W, a, rel, NE, NR, nbden);
    k_mm<<<nbm + nbs, 256>>>(emb, W, rel, NE, NR, nbm);
    k_score<<<(E + 255) / 256, 256>>>(h, r, t, ab, E);
    k_scatter<<<(E * 32 + 255) / 256, 256>>>(h, r, t, E);
    k_out<<<(NE * 32 + 255) / 256, 256>>>(bias, out, NE);
}